// round 16
// baseline (speedup 1.0000x reference)
#include <cuda_runtime.h>
#include <cuda_fp16.h>
#include <stdint.h>

#define T_TOK 8192
#define D_DIM 1024
#define E_EXP 8
#define F_DIM 512
#define NPAIR (T_TOK * 2)

// ---------------- device scratch (~84MB, proven envelope) ----------------
__device__ int   g_topk_idx[NPAIR];
__device__ float g_topk_p[NPAIR];
__device__ int   g_cnt[E_EXP];
__device__ int   g_off[E_EXP];
__device__ int   g_cur[E_EXP];
__device__ int   g_pair_token[NPAIR];
__device__ int   g_pair_pos[NPAIR];
__device__ __align__(256) __half g_H[(size_t)(NPAIR + 128) * F_DIM];   // 16.5 MB
__device__ float g_O[(size_t)NPAIR * D_DIM];                           // 64 MB

// ---------------- helpers ----------------
__device__ __forceinline__ uint32_t smem_u32(const void* p) {
    uint32_t a;
    asm("{ .reg .u64 t; cvta.to.shared.u64 t, %1; cvt.u32.u64 %0, t; }"
        : "=r"(a) : "l"(p));
    return a;
}
__device__ __forceinline__ void mma16816h(float* c, const uint32_t* a, const uint32_t* b) {
    asm volatile(
        "mma.sync.aligned.m16n8k16.row.col.f32.f16.f16.f32 "
        "{%0,%1,%2,%3}, {%4,%5,%6,%7}, {%8,%9}, {%0,%1,%2,%3};"
        : "+f"(c[0]), "+f"(c[1]), "+f"(c[2]), "+f"(c[3])
        : "r"(a[0]), "r"(a[1]), "r"(a[2]), "r"(a[3]), "r"(b[0]), "r"(b[1]));
}
__device__ __forceinline__ void ldsm4(uint32_t* r, uint32_t addr) {
    asm volatile("ldmatrix.sync.aligned.m8n8.x4.shared.b16 {%0,%1,%2,%3}, [%4];"
        : "=r"(r[0]), "=r"(r[1]), "=r"(r[2]), "=r"(r[3]) : "r"(addr));
}
__device__ __forceinline__ void ldsm4t(uint32_t* r, uint32_t addr) {
    asm volatile("ldmatrix.sync.aligned.m8n8.x4.trans.shared.b16 {%0,%1,%2,%3}, [%4];"
        : "=r"(r[0]), "=r"(r[1]), "=r"(r[2]), "=r"(r[3]) : "r"(addr));
}
__device__ __forceinline__ uint32_t cvt2h(float a, float b) {
    __half2 h = __floats2half2_rn(a, b);
    return *reinterpret_cast<uint32_t*>(&h);
}

// ---------------- small kernels (proven) ----------------
__global__ void init_kernel() {
    if (threadIdx.x < E_EXP) g_cnt[threadIdx.x] = 0;
}

__global__ void router_kernel(const float* __restrict__ x,
                              const float* __restrict__ wr) {
    int t = blockIdx.x;
    int tid = threadIdx.x;
    float acc[E_EXP];
#pragma unroll
    for (int e = 0; e < E_EXP; e++) acc[e] = 0.f;
    const float* xr = x + (size_t)t * D_DIM;
    for (int i = tid; i < D_DIM; i += 128) {
        float xv = xr[i];
#pragma unroll
        for (int e = 0; e < E_EXP; e++) acc[e] += xv * wr[e * D_DIM + i];
    }
    __shared__ float sh[E_EXP][128];
#pragma unroll
    for (int e = 0; e < E_EXP; e++) sh[e][tid] = acc[e];
    __syncthreads();
    for (int s = 64; s > 0; s >>= 1) {
        if (tid < s) {
#pragma unroll
            for (int e = 0; e < E_EXP; e++) sh[e][tid] += sh[e][tid + s];
        }
        __syncthreads();
    }
    if (tid == 0) {
        float l[E_EXP];
#pragma unroll
        for (int e = 0; e < E_EXP; e++) l[e] = sh[e][0];
        int i1 = 0;
#pragma unroll
        for (int e = 1; e < E_EXP; e++) if (l[e] > l[i1]) i1 = e;
        int i2 = (i1 == 0) ? 1 : 0;
#pragma unroll
        for (int e = 0; e < E_EXP; e++) if (e != i1 && l[e] > l[i2]) i2 = e;
        float ex = __expf(l[i2] - l[i1]);
        float inv = 1.f / (1.f + ex);
        g_topk_idx[t * 2 + 0] = i1; g_topk_p[t * 2 + 0] = inv;
        g_topk_idx[t * 2 + 1] = i2; g_topk_p[t * 2 + 1] = ex * inv;
        atomicAdd(&g_cnt[i1], 1);
        atomicAdd(&g_cnt[i2], 1);
    }
}

__global__ void prefix_kernel() {
    if (threadIdx.x == 0) {
        int acc = 0;
        for (int e = 0; e < E_EXP; e++) { g_off[e] = acc; g_cur[e] = acc; acc += g_cnt[e]; }
    }
}

__global__ void scatter_kernel() {
    int t = blockIdx.x * blockDim.x + threadIdx.x;
    if (t >= T_TOK) return;
#pragma unroll
    for (int k = 0; k < 2; k++) {
        int e = g_topk_idx[t * 2 + k];
        int pos = atomicAdd(&g_cur[e], 1);
        g_pair_token[pos] = t;
        g_pair_pos[t * 2 + k] = pos;
    }
}

// A smem: [m][k32] rows padded to 40 shorts (80B rows - R8-proven ldsm geometry),
// double buffered. B smem: k-major [32][136] shorts (R13-proven trans geometry),
// double buffered. Totals: A 20480B + B 17408B = 37888B static (< 48KB).
#define PADK 40
#define BPADB 136
#define BUFA (128 * PADK * 2)
#define BUFBB (32 * BPADB * 2)

// ---------------- GEMM1: H = silu(X Wg) * (X Wu), fp16, K-stage 32 ----------------
__global__ void __launch_bounds__(256) gemm1_mma(const float* __restrict__ x,
                                                 const float* __restrict__ wg,
                                                 const float* __restrict__ wu) {
    int e = blockIdx.z;
    int cnt = g_cnt[e];
    int m0 = blockIdx.y * 128;
    if (m0 >= cnt) return;
    int base = g_off[e];
    int f0 = blockIdx.x * 64;

    __shared__ unsigned short As_h[2][128][PADK];
    __shared__ unsigned short Bs_h[2][32][BPADB];

    int tid = threadIdx.x;
    int lid = tid & 31, wid = tid >> 5;
    int wm = wid >> 1, wn = wid & 1;

    uint32_t aH = smem_u32(As_h);
    uint32_t bH = smem_u32(Bs_h);

    int grp = lid >> 3, lr = lid & 7;
    uint32_t aofs = (uint32_t)(((wm * 32 + (grp & 1) * 8 + lr) * PADK + (grp >> 1) * 8) * 2);
    uint32_t bofs = (uint32_t)((((grp & 1) * 8 + lr) * BPADB + wn * 32 + (grp >> 1) * 8) * 2);

    float acc_g[2][4][4], acc_u[2][4][4];
#pragma unroll
    for (int a = 0; a < 2; a++)
#pragma unroll
        for (int b = 0; b < 4; b++)
#pragma unroll
            for (int c = 0; c < 4; c++) { acc_g[a][b][c] = 0.f; acc_u[a][b][c] = 0.f; }

    // A loads: one smem row per thread, 16 of 32 k per stage
    int row0 = tid >> 1, kh = (tid & 1) * 16;
    int am = m0 + row0;
    int mytok = g_pair_token[base + ((am < cnt) ? am : 0)];
    const float* asrc = x + (size_t)mytok * D_DIM + kh;
    // B loads: k=tid>>3 (0..31), n=(tid&7)*16 (0..112); coalesced float4 along f
    int bk = tid >> 3, bn = (tid & 7) * 16;
    size_t eoff = (size_t)e * D_DIM * F_DIM;
    const float* bsrc = ((bn < 64) ? wg : wu) + eoff + f0 + (bn & 63);

    float4 apf[4], bv[4];
    const int NS = D_DIM / 32;   // 32 stages

#pragma unroll
    for (int q = 0; q < 4; ++q) apf[q] = *(const float4*)(asrc + 4 * q);
#pragma unroll
    for (int q = 0; q < 4; ++q) bv[q] = *(const float4*)(bsrc + (size_t)bk * F_DIM + 4 * q);

    for (int s = 0; s < NS; ++s) {
        int buf = s & 1;
        uint32_t ah8[8], bh8[8];
#pragma unroll
        for (int q = 0; q < 4; ++q) {
            ah8[2 * q]     = cvt2h(apf[q].x, apf[q].y);
            ah8[2 * q + 1] = cvt2h(apf[q].z, apf[q].w);
            bh8[2 * q]     = cvt2h(bv[q].x, bv[q].y);
            bh8[2 * q + 1] = cvt2h(bv[q].z, bv[q].w);
        }
        *(uint4*)&As_h[buf][row0][kh]     = *(uint4*)(ah8);
        *(uint4*)&As_h[buf][row0][kh + 8] = *(uint4*)(ah8 + 4);
        *(uint4*)&Bs_h[buf][bk][bn]     = *(uint4*)(bh8);
        *(uint4*)&Bs_h[buf][bk][bn + 8] = *(uint4*)(bh8 + 4);
        __syncthreads();

        if (s + 1 < NS) {
            int kn = (s + 1) * 32;
#pragma unroll
            for (int q = 0; q < 4; ++q) apf[q] = *(const float4*)(asrc + kn + 4 * q);
#pragma unroll
            for (int q = 0; q < 4; ++q)
                bv[q] = *(const float4*)(bsrc + (size_t)(kn + bk) * F_DIM + 4 * q);
        }

        uint32_t bufoA = (uint32_t)(buf * BUFA);
        uint32_t bufoB = (uint32_t)(buf * BUFBB);
#pragma unroll
        for (int kk = 0; kk < 2; ++kk) {
            uint32_t ah[2][4];
#pragma unroll
            for (int mi = 0; mi < 2; ++mi) {
                uint32_t ao = bufoA + aofs + (uint32_t)(mi * 16 * PADK * 2 + kk * 32);
                ldsm4(ah[mi], aH + ao);
            }
#pragma unroll
            for (int jj = 0; jj < 2; ++jj) {
                uint32_t bo = bufoB + bofs + (uint32_t)(kk * 16 * BPADB * 2 + jj * 32);
                uint32_t gh[4], uh[4];
                ldsm4t(gh, bH + bo);
                ldsm4t(uh, bH + bo + 128);   // up: +64 cols
#pragma unroll
                for (int jo = 0; jo < 2; ++jo) {
                    int j = jj * 2 + jo;
#pragma unroll
                    for (int mi = 0; mi < 2; ++mi) {
                        mma16816h(acc_g[mi][j], ah[mi], gh + jo * 2);
                        mma16816h(acc_u[mi][j], ah[mi], uh + jo * 2);
                    }
                }
            }
        }
    }

    // epilogue: silu(g)*u, write fp16 H (proven)
#pragma unroll
    for (int mi = 0; mi < 2; ++mi) {
#pragma unroll
        for (int j = 0; j < 4; ++j) {
            int row = m0 + wm * 32 + mi * 16 + (lid >> 2);
            int col = f0 + wn * 32 + j * 8 + (lid & 3) * 2;
#pragma unroll
            for (int half = 0; half < 2; ++half) {
                int r = row + half * 8;
                if (r < cnt) {
                    float g0 = acc_g[mi][j][half * 2 + 0];
                    float g1 = acc_g[mi][j][half * 2 + 1];
                    float u0 = acc_u[mi][j][half * 2 + 0];
                    float u1 = acc_u[mi][j][half * 2 + 1];
                    float h0 = u0 * g0 / (1.f + __expf(-g0));
                    float h1 = u1 * g1 / (1.f + __expf(-g1));
                    size_t o = (size_t)(base + r) * F_DIM + col;
                    *(uint32_t*)&g_H[o] = cvt2h(h0, h1);
                }
            }
        }
    }
}

// ---------------- GEMM2: O = H @ Wd, fp16, K-stage 32 ----------------
__global__ void __launch_bounds__(256) gemm2_mma(const float* __restrict__ wd) {
    int e = blockIdx.z;
    int cnt = g_cnt[e];
    int m0 = blockIdx.y * 128;
    if (m0 >= cnt) return;
    int base = g_off[e];
    int n0 = blockIdx.x * 128;

    __shared__ unsigned short As_h[2][128][PADK];
    __shared__ unsigned short Bs_h[2][32][BPADB];

    int tid = threadIdx.x;
    int lid = tid & 31, wid = tid >> 5;
    int wm = wid >> 1, wn = wid & 1;

    uint32_t aH = smem_u32(As_h);
    uint32_t bH = smem_u32(Bs_h);

    int grp = lid >> 3, lr = lid & 7;
    uint32_t aofs = (uint32_t)(((wm * 32 + (grp & 1) * 8 + lr) * PADK + (grp >> 1) * 8) * 2);
    uint32_t bofs = (uint32_t)((((grp & 1) * 8 + lr) * BPADB + wn * 64 + (grp >> 1) * 8) * 2);

    float acc[2][8][4];
#pragma unroll
    for (int a = 0; a < 2; a++)
#pragma unroll
        for (int b = 0; b < 8; b++)
#pragma unroll
            for (int c = 0; c < 4; c++) acc[a][b][c] = 0.f;

    // A loads: H is fp16 already; one row per thread, 16 halves = 1 uint4 per half-row
    int row0 = tid >> 1, kh = (tid & 1) * 16;
    int am = m0 + row0;
    size_t arow = (size_t)(base + ((am < cnt) ? am : 0)) * F_DIM + kh;
    // B loads: k=tid>>3 (0..31), n=(tid&7)*16
    int bk = tid >> 3, bn = (tid & 7) * 16;
    const float* bsrc = wd + (size_t)e * F_DIM * D_DIM + n0 + bn;

    uint4 aph[2];
    float4 bv[4];
    const int NS = F_DIM / 32;   // 16 stages

    aph[0] = *(const uint4*)(g_H + arow);
    aph[1] = *(const uint4*)(g_H + arow + 8);
#pragma unroll
    for (int q = 0; q < 4; ++q) bv[q] = *(const float4*)(bsrc + (size_t)bk * D_DIM + 4 * q);

    for (int s = 0; s < NS; ++s) {
        int buf = s & 1;
        uint32_t bh8[8];
#pragma unroll
        for (int q = 0; q < 4; ++q) {
            bh8[2 * q]     = cvt2h(bv[q].x, bv[q].y);
            bh8[2 * q + 1] = cvt2h(bv[q].z, bv[q].w);
        }
        *(uint4*)&As_h[buf][row0][kh]     = aph[0];
        *(uint4*)&As_h[buf][row0][kh + 8] = aph[1];
        *(uint4*)&Bs_h[buf][bk][bn]     = *(uint4*)(bh8);
        *(uint4*)&Bs_h[buf][bk][bn + 8] = *(uint4*)(bh8 + 4);
        __syncthreads();

        if (s + 1 < NS) {
            int kn = (s + 1) * 32;
            aph[0] = *(const uint4*)(g_H + arow + kn);
            aph[1] = *(const uint4*)(g_H + arow + kn + 8);
#pragma unroll
            for (int q = 0; q < 4; ++q)
                bv[q] = *(const float4*)(bsrc + (size_t)(kn + bk) * D_DIM + 4 * q);
        }

        uint32_t bufoA = (uint32_t)(buf * BUFA);
        uint32_t bufoB = (uint32_t)(buf * BUFBB);
#pragma unroll
        for (int kk = 0; kk < 2; ++kk) {
            uint32_t ah[2][4];
#pragma unroll
            for (int mi = 0; mi < 2; ++mi) {
                uint32_t ao = bufoA + aofs + (uint32_t)(mi * 16 * PADK * 2 + kk * 32);
                ldsm4(ah[mi], aH + ao);
            }
#pragma unroll
            for (int jj = 0; jj < 4; ++jj) {
                uint32_t bo = bufoB + bofs + (uint32_t)(kk * 16 * BPADB * 2 + jj * 32);
                uint32_t bh[4];
                ldsm4t(bh, bH + bo);
#pragma unroll
                for (int jo = 0; jo < 2; ++jo) {
                    int j = jj * 2 + jo;
#pragma unroll
                    for (int mi = 0; mi < 2; ++mi) {
                        mma16816h(acc[mi][j], ah[mi], bh + jo * 2);
                    }
                }
            }
        }
    }

#pragma unroll
    for (int mi = 0; mi < 2; ++mi) {
#pragma unroll
        for (int j = 0; j < 8; ++j) {
            int row = m0 + wm * 32 + mi * 16 + (lid >> 2);
            int col = n0 + wn * 64 + j * 8 + (lid & 3) * 2;
#pragma unroll
            for (int half = 0; half < 2; ++half) {
                int r = row + half * 8;
                if (r < cnt) {
                    float2 v = make_float2(acc[mi][j][half * 2 + 0],
                                           acc[mi][j][half * 2 + 1]);
                    *(float2*)&g_O[(size_t)(base + r) * D_DIM + col] = v;
                }
            }
        }
    }
}

// ---------------- combine (proven) ----------------
__global__ void combine_kernel(float* __restrict__ out) {
    int idx = blockIdx.x * blockDim.x + threadIdx.x;
    int t = idx / (D_DIM / 4);
    int j4 = (idx % (D_DIM / 4)) * 4;
    float p0 = g_topk_p[t * 2 + 0];
    float p1 = g_topk_p[t * 2 + 1];
    int q0 = g_pair_pos[t * 2 + 0];
    int q1 = g_pair_pos[t * 2 + 1];
    float4 a = *(const float4*)(g_O + (size_t)q0 * D_DIM + j4);
    float4 b = *(const float4*)(g_O + (size_t)q1 * D_DIM + j4);
    float4 o;
    o.x = p0 * a.x + p1 * b.x;
    o.y = p0 * a.y + p1 * b.y;
    o.z = p0 * a.z + p1 * b.z;
    o.w = p0 * a.w + p1 * b.w;
    *(float4*)(out + (size_t)t * D_DIM + j4) = o;
}

extern "C" void kernel_launch(void* const* d_in, const int* in_sizes, int n_in,
                              void* d_out, int out_size) {
    const float* x  = (const float*)d_in[0];
    const float* wr = (const float*)d_in[1];
    const float* wg = (const float*)d_in[2];
    const float* wu = (const float*)d_in[3];
    const float* wd = (const float*)d_in[4];
    float* out = (float*)d_out;

    init_kernel<<<1, 32>>>();
    router_kernel<<<T_TOK, 128>>>(x, wr);
    prefix_kernel<<<1, 32>>>();
    scatter_kernel<<<T_TOK / 256, 256>>>();

    gemm1_mma<<<dim3(F_DIM / 64, NPAIR / 128, E_EXP), 256>>>(x, wg, wu);
    gemm2_mma<<<dim3(D_DIM / 128, NPAIR / 128, E_EXP), 256>>>(wd);

    combine_kernel<<<(T_TOK * D_DIM / 4) / 256, 256>>>(out);
}